// round 8
// baseline (speedup 1.0000x reference)
#include <cuda_runtime.h>
#include <cuda_fp16.h>
#include <cstdint>

#define DEVINL __device__ __forceinline__

// ---------------- problem constants ----------------
static constexpr int BATCH = 4;
static constexpr int NSEQ  = 4096;
static constexpr int DDIM  = 512;
static constexpr float CLOG2E = 0.09016844005556021f;  // scale*log2(e), folded into alpha
static constexpr float SQ = 20.0f;                      // int8 quant scale (q and k)
static constexpr float ALPHA = CLOG2E / (SQ * SQ);      // logit2 = ALPHA*C1 + BETA*C2
static constexpr float BETA  = ALPHA / 128.0f;

// ---------------- tiling ----------------
static constexpr int MT    = 128;             // q rows per unit
static constexpr int NTILE = 128;             // kv rows per unit
static constexpr int KC    = 128;             // s8 k-bytes per chunk (128B smem rows)
static constexpr int CPU   = DDIM / KC;       // 4 chunks per unit
static constexpr int QTILES = BATCH * NSEQ / MT;     // 128
static constexpr int NTC    = NSEQ / NTILE;          // 32
static constexpr int UNITS  = QTILES * NTC;          // 4096 work units
static constexpr int STAGES = 3;

static constexpr int TB  = MT * KC;               // 16384 bytes per tile (all 4 tiles equal)
static constexpr int STB = 4 * TB;                // Ah|Al|Bh|Bl = 65536 per stage
static constexpr int SMEM_TOTAL = 1024 + STAGES * STB;

// ---------------- scratch (device globals: no allocs allowed) ----------------
__device__ __align__(1024) int8_t g_q8h[(size_t)BATCH * NSEQ * DDIM];
__device__ __align__(1024) int8_t g_q8l[(size_t)BATCH * NSEQ * DDIM];
__device__ __align__(1024) int8_t g_k8h[(size_t)BATCH * NSEQ * DDIM];
__device__ __align__(1024) int8_t g_k8l[(size_t)BATCH * NSEQ * DDIM];
__device__ float g_diagexp[BATCH * NSEQ];
__device__ float g_rsum[BATCH * NSEQ];

// ---------------- PTX helpers ----------------
DEVINL uint32_t smem_u32(const void* p) {
    uint32_t a;
    asm("{ .reg .u64 t; cvta.to.shared.u64 t, %1; cvt.u32.u64 %0, t; }"
        : "=r"(a) : "l"(p));
    return a;
}
DEVINL uint32_t sw128(uint32_t off) { return off ^ ((off >> 3) & 0x70); }

DEVINL void cp_async16(uint32_t dst, const void* src) {
    asm volatile("cp.async.cg.shared.global [%0], [%1], 16;"
                 :: "r"(dst), "l"(src) : "memory");
}
DEVINL void cp_commit() { asm volatile("cp.async.commit_group;" ::: "memory"); }
template <int N>
DEVINL void cp_wait_group() { asm volatile("cp.async.wait_group %0;" :: "n"(N) : "memory"); }

DEVINL void ldsm4(uint32_t (&r)[4], uint32_t addr) {
    asm volatile("ldmatrix.sync.aligned.m8n8.x4.shared.b16 {%0,%1,%2,%3}, [%4];"
                 : "=r"(r[0]), "=r"(r[1]), "=r"(r[2]), "=r"(r[3]) : "r"(addr));
}
// s8 IMMA: D(s32 x4) += A(s8 16x32) * B(s8 32x8)
DEVINL void imma(int* d, const uint32_t* a, uint32_t b0, uint32_t b1) {
    asm volatile(
        "mma.sync.aligned.m16n8k32.row.col.s32.s8.s8.s32 "
        "{%0,%1,%2,%3}, {%4,%5,%6,%7}, {%8,%9}, {%0,%1,%2,%3};"
        : "+r"(d[0]), "+r"(d[1]), "+r"(d[2]), "+r"(d[3])
        : "r"(a[0]), "r"(a[1]), "r"(a[2]), "r"(a[3]), "r"(b0), "r"(b1));
}
DEVINL float ex2(float x) {
    float y;
    asm("ex2.approx.ftz.f32 %0, %1;" : "=f"(y) : "f"(x));
    return y;
}
DEVINL int clamp127(int v) { return v < -127 ? -127 : (v > 127 ? 127 : v); }

// ---------------- prep: fp32 -> s8 hi/lo (15-bit effective) ----------------
__global__ void __launch_bounds__(512) prep_kernel(const float* __restrict__ q,
                                                   const float* __restrict__ kv) {
    size_t idx = (size_t)blockIdx.x * 512 + threadIdx.x;  // float4 id (exact grid)
    size_t row = idx >> 7;                                // 128 float4 per 512-row
    int    dp  = (int)(idx & 127) << 2;
    size_t bo  = (row * DDIM + dp) >> 2;                  // uint32 slot

    {
        float4 a = reinterpret_cast<const float4*>(q)[idx];
        float s[4] = {a.x * SQ, a.y * SQ, a.z * SQ, a.w * SQ};
        uint32_t ph = 0, pl = 0;
#pragma unroll
        for (int i = 0; i < 4; ++i) {
            int h = clamp127(__float2int_rn(s[i]));
            int l = clamp127(__float2int_rn((s[i] - (float)h) * 128.0f));
            ph |= (uint32_t)(h & 255) << (8 * i);
            pl |= (uint32_t)(l & 255) << (8 * i);
        }
        reinterpret_cast<uint32_t*>(g_q8h)[bo] = ph;
        reinterpret_cast<uint32_t*>(g_q8l)[bo] = pl;
    }
    {
        float4 a = reinterpret_cast<const float4*>(kv)[idx];
        float s[4] = {a.x * SQ, a.y * SQ, a.z * SQ, a.w * SQ};
        uint32_t ph = 0, pl = 0;
#pragma unroll
        for (int i = 0; i < 4; ++i) {
            int h = clamp127(__float2int_rn(s[i]));
            int l = clamp127(__float2int_rn((s[i] - (float)h) * 128.0f));
            ph |= (uint32_t)(h & 255) << (8 * i);
            pl |= (uint32_t)(l & 255) << (8 * i);
        }
        reinterpret_cast<uint32_t*>(g_k8h)[bo] = ph;
        reinterpret_cast<uint32_t*>(g_k8l)[bo] = pl;
    }
}

// ---------------- exact fp32 diagonal + zero the row-sum accumulators ----------------
__global__ void __launch_bounds__(256) diag_kernel(const float* __restrict__ q,
                                                   const float* __restrict__ kv) {
    int row  = blockIdx.x * 8 + (threadIdx.x >> 5);
    int lane = threadIdx.x & 31;
    const float* qr = q  + (size_t)row * DDIM;
    const float* kr = kv + (size_t)row * DDIM;
    float s = 0.f;
#pragma unroll
    for (int i = 0; i < 16; ++i) s += qr[lane + 32 * i] * kr[lane + 32 * i];
#pragma unroll
    for (int off = 16; off; off >>= 1) s += __shfl_xor_sync(0xffffffffu, s, off);
    if (lane == 0) {
        g_diagexp[row] = exp2f(CLOG2E * s);
        g_rsum[row] = 0.f;
    }
}

// ---------------- main int8 GEMM + normalizer: persistent over all SMs ----------------
__global__ void __launch_bounds__(256, 1) main_kernel(int nsm) {
    extern __shared__ char smem_raw[];
    const uint32_t st0 = (smem_u32(smem_raw) + 1023u) & ~1023u;

    const int tid  = threadIdx.x;
    const int wid  = tid >> 5;
    const int lane = tid & 31;
    const int bid  = blockIdx.x;

    // per-thread cp.async vector descriptors: 128 rows x 8 x 16B = 1024 vectors
    // per tile, 4 per thread per tile
    int goff[4]; uint32_t sdst[4];
#pragma unroll
    for (int i = 0; i < 4; ++i) {
        int v = tid + i * 256, r = v >> 3, j = v & 7;
        goff[i] = r * DDIM + j * 16;
        sdst[i] = sw128((uint32_t)(r * 128 + j * 16));
    }

    // unit u: qt = u & 127, nt = u >> 7 (a wave shares one kv tile -> L2 reuse)
    auto issue = [&](int it) {
        const int u = bid + (it >> 2) * nsm;
        if (u >= UNITS) { cp_commit(); return; }   // keep group counts uniform
        const int qt = u & (QTILES - 1), nt = u >> 7, cc = it & 3;
        const uint32_t s = st0 + (it % STAGES) * STB;
        const size_t qb = (size_t)qt * MT * DDIM + cc * KC;
        const size_t kb = ((size_t)(qt >> 5) * NSEQ + (size_t)nt * NTILE) * DDIM + cc * KC;
#pragma unroll
        for (int i = 0; i < 4; ++i) cp_async16(s + sdst[i],          g_q8h + qb + goff[i]);
#pragma unroll
        for (int i = 0; i < 4; ++i) cp_async16(s + TB + sdst[i],     g_q8l + qb + goff[i]);
#pragma unroll
        for (int i = 0; i < 4; ++i) cp_async16(s + 2 * TB + sdst[i], g_k8h + kb + goff[i]);
#pragma unroll
        for (int i = 0; i < 4; ++i) cp_async16(s + 3 * TB + sdst[i], g_k8l + kb + goff[i]);
        cp_commit();
    };

    // warp tile 32x64: 4 M-warps x 2 N-warps
    const int m0 = (wid & 3) * 32;
    const int n0 = (wid >> 2) * 64;
    const int lr  = lane & 15;          // ldmatrix row within 16
    const int lcb = (lane >> 4) * 16;   // ldmatrix 16B column half

    uint32_t aBase[2], aSw[2], bBase[4], bSw[4];
#pragma unroll
    for (int f = 0; f < 2; ++f) {
        int ra = m0 + f * 16 + lr;
        aBase[f] = (uint32_t)(ra * 128); aSw[f] = (uint32_t)((ra & 7) << 4);
    }
#pragma unroll
    for (int f = 0; f < 4; ++f) {
        int rb = n0 + f * 16 + lr;
        bBase[f] = (uint32_t)(rb * 128); bSw[f] = (uint32_t)((rb & 7) << 4);
    }

    // s32 accumulators: C1 = qh*kh ; C2 = ql*kh + qh*kl (combined, weight 1/128)
    int c1[2][8][4], c2[2][8][4];
#pragma unroll
    for (int mf = 0; mf < 2; ++mf)
#pragma unroll
        for (int nf = 0; nf < 8; ++nf)
#pragma unroll
            for (int k = 0; k < 4; ++k) { c1[mf][nf][k] = 0; c2[mf][nf][k] = 0; }

    const int nunits = (UNITS - bid + nsm - 1) / nsm;
    const int nits   = nunits * CPU;

    issue(0);
    issue(1);

    for (int it = 0; it < nits; ++it) {
        cp_wait_group<1>();
        __syncthreads();
        issue(it + 2);

        const uint32_t sAh = st0 + (it % STAGES) * STB;
        const uint32_t sAl = sAh + TB;
        const uint32_t sBh = sAh + 2 * TB;
        const uint32_t sBl = sAh + 3 * TB;

#pragma unroll
        for (int kk = 0; kk < 4; ++kk) {        // 4 x k32 per 128B chunk
            const uint32_t cb = (uint32_t)(kk * 32) + lcb;
            uint32_t ah[2][4], al[2][4], bh[4][4], bl[4][4];
#pragma unroll
            for (int f = 0; f < 4; ++f) ldsm4(bh[f], sBh + bBase[f] + (cb ^ bSw[f]));
#pragma unroll
            for (int f = 0; f < 2; ++f) ldsm4(ah[f], sAh + aBase[f] + (cb ^ aSw[f]));
#pragma unroll
            for (int f = 0; f < 2; ++f) ldsm4(al[f], sAl + aBase[f] + (cb ^ aSw[f]));
#pragma unroll
            for (int f = 0; f < 4; ++f) ldsm4(bl[f], sBl + bBase[f] + (cb ^ bSw[f]));
#pragma unroll
            for (int mf = 0; mf < 2; ++mf)
#pragma unroll
                for (int f = 0; f < 4; ++f) {
                    imma(c1[mf][2 * f],     ah[mf], bh[f][0], bh[f][2]);
                    imma(c1[mf][2 * f + 1], ah[mf], bh[f][1], bh[f][3]);
                    imma(c2[mf][2 * f],     al[mf], bh[f][0], bh[f][2]);
                    imma(c2[mf][2 * f + 1], al[mf], bh[f][1], bh[f][3]);
                    imma(c2[mf][2 * f],     ah[mf], bl[f][0], bl[f][2]);
                    imma(c2[mf][2 * f + 1], ah[mf], bl[f][1], bl[f][3]);
                }
        }

        if ((it & 3) == 3) {
            // unit epilogue: rowsum of 2^(ALPHA*C1 + BETA*C2) -> global accumulators
            const int qt = (bid + (it >> 2) * nsm) & (QTILES - 1);
            float* rs = g_rsum + qt * MT;
#pragma unroll
            for (int mf = 0; mf < 2; ++mf) {
                float s0 = 0.f, s1 = 0.f;
#pragma unroll
                for (int nf = 0; nf < 8; ++nf) {
                    s0 += ex2(fmaf(BETA, (float)c2[mf][nf][0], ALPHA * (float)c1[mf][nf][0]))
                        + ex2(fmaf(BETA, (float)c2[mf][nf][1], ALPHA * (float)c1[mf][nf][1]));
                    s1 += ex2(fmaf(BETA, (float)c2[mf][nf][2], ALPHA * (float)c1[mf][nf][2]))
                        + ex2(fmaf(BETA, (float)c2[mf][nf][3], ALPHA * (float)c1[mf][nf][3]));
#pragma unroll
                    for (int k = 0; k < 4; ++k) { c1[mf][nf][k] = 0; c2[mf][nf][k] = 0; }
                }
                s0 += __shfl_xor_sync(0xffffffffu, s0, 1);
                s0 += __shfl_xor_sync(0xffffffffu, s0, 2);
                s1 += __shfl_xor_sync(0xffffffffu, s1, 1);
                s1 += __shfl_xor_sync(0xffffffffu, s1, 2);
                if ((lane & 3) == 0) {
                    atomicAdd(&rs[m0 + mf * 16 + (lane >> 2)], s0);
                    atomicAdd(&rs[m0 + mf * 16 + 8 + (lane >> 2)], s1);
                }
            }
        }
    }
}

// ---------------- final: out = diagexp / rowsum ----------------
__global__ void __launch_bounds__(256) out_kernel(float* __restrict__ out) {
    int row = blockIdx.x * 256 + threadIdx.x;
    out[row] = g_diagexp[row] / g_rsum[row];
}

extern "C" void kernel_launch(void* const* d_in, const int* in_sizes, int n_in,
                              void* d_out, int out_size) {
    const float* q  = (const float*)d_in[0];
    const float* kv = (const float*)d_in[1];
    float* out = (float*)d_out;

    int nsm = 0;
    cudaDeviceGetAttribute(&nsm, cudaDevAttrMultiProcessorCount, 0);
    if (nsm <= 0 || nsm > UNITS) nsm = 128;

    prep_kernel<<<4096, 512>>>(q, kv);
    diag_kernel<<<2048, 256>>>(q, kv);

    cudaFuncSetAttribute(main_kernel, cudaFuncAttributeMaxDynamicSharedMemorySize,
                         SMEM_TOTAL);
    main_kernel<<<nsm, 256, SMEM_TOTAL>>>(nsm);

    out_kernel<<<BATCH * NSEQ / 256, 256>>>(out);
}

// round 9
// speedup vs baseline: 3.7137x; 3.7137x over previous
#include <cuda_runtime.h>
#include <cuda_fp16.h>
#include <cstdint>

#define DEVINL __device__ __forceinline__

// ---------------- problem constants ----------------
static constexpr int BATCH = 4;
static constexpr int NSEQ  = 4096;
static constexpr int DDIM  = 512;
// scale * log2(e): logits kept in log2 domain so epilogue is a bare ex2.approx
static constexpr float CLOG2E = 0.09016844005556021f;
static constexpr float LOSCALE = 1024.0f;          // lo term stored pre-scaled
static constexpr float LOINV   = 1.0f / 1024.0f;   // undone in epilogue

// ---------------- tiling ----------------
static constexpr int MT    = 128;            // q rows per unit
static constexpr int NTILE = 256;            // kv rows per unit
static constexpr int KQ    = 1024;           // qcat row: [qh(512) | ql(512)]  fp16
static constexpr int KK    = 512;            // kcat row: [kh(512)]            fp16
static constexpr int KC    = 64;             // k per chunk (128B smem rows)
static constexpr int QTILES = BATCH * NSEQ / MT;   // 128
static constexpr int NTC    = NSEQ / NTILE;        // 16
static constexpr int UNITS  = QTILES * NTC;        // 2048 work units
static constexpr int STAGES = 3;
static constexpr int THREADS = 512;                // 16 warps: 4 M x 4 N

static constexpr int AB  = MT * KC * 2;          // 16384 per A term
static constexpr int BB  = NTILE * KC * 2;       // 32768
static constexpr int STB = 2 * AB + BB;          // 65536 per stage
static constexpr int SMEM_TOTAL = 1024 + STAGES * STB;

// ---------------- scratch (device globals: no allocs allowed) ----------------
__device__ __align__(1024) __half g_qcat[(size_t)BATCH * NSEQ * KQ];
__device__ __align__(1024) __half g_kcat[(size_t)BATCH * NSEQ * KK];
__device__ float g_diagexp[BATCH * NSEQ];
__device__ float g_rsum[BATCH * NSEQ];

// ---------------- PTX helpers ----------------
DEVINL uint32_t smem_u32(const void* p) {
    uint32_t a;
    asm("{ .reg .u64 t; cvta.to.shared.u64 t, %1; cvt.u32.u64 %0, t; }"
        : "=r"(a) : "l"(p));
    return a;
}
DEVINL uint32_t sw128(uint32_t off) { return off ^ ((off >> 3) & 0x70); }

DEVINL void cp_async16(uint32_t dst, const void* src) {
    asm volatile("cp.async.cg.shared.global [%0], [%1], 16;"
                 :: "r"(dst), "l"(src) : "memory");
}
DEVINL void cp_commit() { asm volatile("cp.async.commit_group;" ::: "memory"); }
template <int N>
DEVINL void cp_wait_group() { asm volatile("cp.async.wait_group %0;" :: "n"(N) : "memory"); }

DEVINL void ldsm4(uint32_t (&r)[4], uint32_t addr) {
    asm volatile("ldmatrix.sync.aligned.m8n8.x4.shared.b16 {%0,%1,%2,%3}, [%4];"
                 : "=r"(r[0]), "=r"(r[1]), "=r"(r[2]), "=r"(r[3]) : "r"(addr));
}
// fp16-accumulate MMA: D (2 regs = 4 halves) += A*B
DEVINL void mma_f16acc(uint32_t* d, const uint32_t* a, uint32_t b0, uint32_t b1) {
    asm volatile(
        "mma.sync.aligned.m16n8k16.row.col.f16.f16.f16.f16 "
        "{%0,%1}, {%2,%3,%4,%5}, {%6,%7}, {%0,%1};"
        : "+r"(d[0]), "+r"(d[1])
        : "r"(a[0]), "r"(a[1]), "r"(a[2]), "r"(a[3]), "r"(b0), "r"(b1));
}
DEVINL float ex2(float x) {
    float y;
    asm("ex2.approx.ftz.f32 %0, %1;" : "=f"(y) : "f"(x));
    return y;
}

// ---------------- prep: q -> fp16 hi/lo split (scaled), k -> fp16 hi ----------------
__global__ void __launch_bounds__(512) prep_kernel(const float* __restrict__ q,
                                                   const float* __restrict__ kv) {
    size_t idx = (size_t)blockIdx.x * 512 + threadIdx.x;  // float4 id (exact grid)
    size_t row = idx >> 7;                                // 128 float4 per 512-row
    int    dp  = (int)(idx & 127) << 2;

    {   // q scaled by CLOG2E, split into fp16 hi + lo (lo pre-scaled by 2^10)
        float4 a = reinterpret_cast<const float4*>(q)[idx];
        float sx = a.x * CLOG2E, sy = a.y * CLOG2E, sz = a.z * CLOG2E, sw = a.w * CLOG2E;
        __half hx = __float2half(sx), hy = __float2half(sy);
        __half hz = __float2half(sz), hw = __float2half(sw);
        __half lx = __float2half((sx - __half2float(hx)) * LOSCALE);
        __half ly = __float2half((sy - __half2float(hy)) * LOSCALE);
        __half lz = __float2half((sz - __half2float(hz)) * LOSCALE);
        __half lw = __float2half((sw - __half2float(hw)) * LOSCALE);
        __half* base = g_qcat + row * KQ + dp;
        reinterpret_cast<__half2*>(base)[0]       = __halves2half2(hx, hy);
        reinterpret_cast<__half2*>(base)[1]       = __halves2half2(hz, hw);
        reinterpret_cast<__half2*>(base + 512)[0] = __halves2half2(lx, ly);
        reinterpret_cast<__half2*>(base + 512)[1] = __halves2half2(lz, lw);
    }
    {   // kv: fp16 hi only
        float4 a = reinterpret_cast<const float4*>(kv)[idx];
        __half* base = g_kcat + row * KK + dp;
        reinterpret_cast<__half2*>(base)[0] =
            __halves2half2(__float2half(a.x), __float2half(a.y));
        reinterpret_cast<__half2*>(base)[1] =
            __halves2half2(__float2half(a.z), __float2half(a.w));
    }
}

// ---------------- exact fp32 diagonal + zero the row-sum accumulators ----------------
__global__ void __launch_bounds__(256) diag_kernel(const float* __restrict__ q,
                                                   const float* __restrict__ kv) {
    int row  = blockIdx.x * 8 + (threadIdx.x >> 5);
    int lane = threadIdx.x & 31;
    const float* qr = q  + (size_t)row * DDIM;
    const float* kr = kv + (size_t)row * DDIM;
    float s = 0.f;
#pragma unroll
    for (int i = 0; i < 16; ++i) s += qr[lane + 32 * i] * kr[lane + 32 * i];
#pragma unroll
    for (int off = 16; off; off >>= 1) s += __shfl_xor_sync(0xffffffffu, s, off);
    if (lane == 0) {
        g_diagexp[row] = exp2f(CLOG2E * s);
        g_rsum[row] = 0.f;
    }
}

// ---------------- main GEMM + normalizer: persistent, 16 warps/CTA ----------------
__global__ void __launch_bounds__(THREADS, 1) main_kernel(int nsm) {
    extern __shared__ char smem_raw[];
    const uint32_t st0 = (smem_u32(smem_raw) + 1023u) & ~1023u;

    const int tid  = threadIdx.x;
    const int wid  = tid >> 5;
    const int lane = tid & 31;
    const int bid  = blockIdx.x;

    // per-thread cp.async vector descriptors (16B vectors)
    // q tiles: 1024 vectors each -> 2 per thread; k tile: 2048 -> 4 per thread
    int qoff[2]; uint32_t qdst[2];
#pragma unroll
    for (int i = 0; i < 2; ++i) {
        int v = tid + i * THREADS, r = v >> 3, j = v & 7;
        qoff[i] = r * KQ + j * 8;
        qdst[i] = sw128((uint32_t)(r * 128 + j * 16));
    }
    int koff[4]; uint32_t kdst[4];
#pragma unroll
    for (int i = 0; i < 4; ++i) {
        int v = tid + i * THREADS, r = v >> 3, j = v & 7;
        koff[i] = r * KK + j * 8;
        kdst[i] = sw128((uint32_t)(r * 128 + j * 16));
    }

    // unit u = nt*128 + qt : one wave shares a kv supertile (L2 reuse)
    auto issue = [&](int it) {
        const int u = bid + (it >> 3) * nsm;
        if (u >= UNITS) { cp_commit(); return; }   // keep group counts uniform
        const int qt = u & (QTILES - 1), nt = u >> 7, cc = it & 7;
        const uint32_t sAh = st0 + (it % STAGES) * STB;
        const uint32_t sAl = sAh + AB;
        const uint32_t sB  = sAh + 2 * AB;
        const __half* qs = g_qcat + (size_t)qt * MT * KQ + cc * KC;
#pragma unroll
        for (int i = 0; i < 2; ++i) cp_async16(sAh + qdst[i], qs + qoff[i]);
#pragma unroll
        for (int i = 0; i < 2; ++i) cp_async16(sAl + qdst[i], qs + 512 + qoff[i]);
        const __half* ks = g_kcat +
            ((size_t)(qt >> 5) * NSEQ + (size_t)nt * NTILE) * KK + cc * KC;
#pragma unroll
        for (int i = 0; i < 4; ++i) cp_async16(sB + kdst[i], ks + koff[i]);
        cp_commit();
    };

    // warp tile: 4 M-warps x 4 N-warps, each 32x64
    const int m0 = (wid & 3) * 32;
    const int n0 = (wid >> 2) * 64;
    const int lr  = lane & 15;          // ldmatrix row within 16
    const int lcb = (lane >> 4) * 16;   // ldmatrix 16B column group

    uint32_t aBase[2], aSw[2], bBase[4], bSw[4];
#pragma unroll
    for (int f = 0; f < 2; ++f) {
        int ra = m0 + f * 16 + lr;
        aBase[f] = (uint32_t)(ra * 128); aSw[f] = (uint32_t)((ra & 7) << 4);
    }
#pragma unroll
    for (int f = 0; f < 4; ++f) {
        int rb = n0 + f * 16 + lr;
        bBase[f] = (uint32_t)(rb * 128); bSw[f] = (uint32_t)((rb & 7) << 4);
    }

    // fp16 accumulators: hi and lo kept separate, combined in fp32 at epilogue
    uint32_t ch[2][8][2], cl[2][8][2];
#pragma unroll
    for (int mf = 0; mf < 2; ++mf)
#pragma unroll
        for (int nf = 0; nf < 8; ++nf) {
            ch[mf][nf][0] = 0u; ch[mf][nf][1] = 0u;
            cl[mf][nf][0] = 0u; cl[mf][nf][1] = 0u;
        }

    const int nunits = (UNITS - bid + nsm - 1) / nsm;   // bid < nsm <= UNITS
    const int nits   = nunits * 8;

    issue(0);
    issue(1);

    for (int it = 0; it < nits; ++it) {
        cp_wait_group<1>();
        __syncthreads();
        issue(it + 2);

        const uint32_t sAh = st0 + (it % STAGES) * STB;
        const uint32_t sAl = sAh + AB;
        const uint32_t sB  = sAh + 2 * AB;

#pragma unroll
        for (int kk = 0; kk < 4; ++kk) {
            const uint32_t cb = (uint32_t)(kk * 32) + lcb;
            uint32_t b[4][4], ah[2][4], al[2][4];
#pragma unroll
            for (int f = 0; f < 4; ++f) ldsm4(b[f],  sB  + bBase[f] + (cb ^ bSw[f]));
#pragma unroll
            for (int f = 0; f < 2; ++f) ldsm4(ah[f], sAh + aBase[f] + (cb ^ aSw[f]));
#pragma unroll
            for (int f = 0; f < 2; ++f) ldsm4(al[f], sAl + aBase[f] + (cb ^ aSw[f]));
            // hi term
#pragma unroll
            for (int mf = 0; mf < 2; ++mf)
#pragma unroll
                for (int g = 0; g < 4; ++g) {
                    mma_f16acc(ch[mf][2 * g],     ah[mf], b[g][0], b[g][2]);
                    mma_f16acc(ch[mf][2 * g + 1], ah[mf], b[g][1], b[g][3]);
                }
            // lo term (separate fp16 accumulators, same B fragments)
#pragma unroll
            for (int mf = 0; mf < 2; ++mf)
#pragma unroll
                for (int g = 0; g < 4; ++g) {
                    mma_f16acc(cl[mf][2 * g],     al[mf], b[g][0], b[g][2]);
                    mma_f16acc(cl[mf][2 * g + 1], al[mf], b[g][1], b[g][3]);
                }
        }

        if ((it & 7) == 7) {
            // unit epilogue: rowsum of 2^(hi + lo/1024) -> global accumulators
            const int qt = (bid + (it >> 3) * nsm) & (QTILES - 1);
            float* rs = g_rsum + qt * MT;
#pragma unroll
            for (int mf = 0; mf < 2; ++mf) {
                float s0 = 0.f, s1 = 0.f;
#pragma unroll
                for (int nf = 0; nf < 8; ++nf) {
                    float2 h0 = __half22float2(*reinterpret_cast<__half2*>(&ch[mf][nf][0]));
                    float2 h1 = __half22float2(*reinterpret_cast<__half2*>(&ch[mf][nf][1]));
                    float2 l0 = __half22float2(*reinterpret_cast<__half2*>(&cl[mf][nf][0]));
                    float2 l1 = __half22float2(*reinterpret_cast<__half2*>(&cl[mf][nf][1]));
                    s0 += ex2(fmaf(l0.x, LOINV, h0.x)) + ex2(fmaf(l0.y, LOINV, h0.y));
                    s1 += ex2(fmaf(l1.x, LOINV, h1.x)) + ex2(fmaf(l1.y, LOINV, h1.y));
                    ch[mf][nf][0] = 0u; ch[mf][nf][1] = 0u;
                    cl[mf][nf][0] = 0u; cl[mf][nf][1] = 0u;
                }
                s0 += __shfl_xor_sync(0xffffffffu, s0, 1);
                s0 += __shfl_xor_sync(0xffffffffu, s0, 2);
                s1 += __shfl_xor_sync(0xffffffffu, s1, 1);
                s1 += __shfl_xor_sync(0xffffffffu, s1, 2);
                if ((lane & 3) == 0) {
                    atomicAdd(&rs[m0 + mf * 16 + (lane >> 2)], s0);
                    atomicAdd(&rs[m0 + mf * 16 + 8 + (lane >> 2)], s1);
                }
            }
        }
    }
}

// ---------------- final: out = diagexp / rowsum ----------------
__global__ void __launch_bounds__(256) out_kernel(float* __restrict__ out) {
    int row = blockIdx.x * 256 + threadIdx.x;
    out[row] = g_diagexp[row] / g_rsum[row];
}

extern "C" void kernel_launch(void* const* d_in, const int* in_sizes, int n_in,
                              void* d_out, int out_size) {
    const float* q  = (const float*)d_in[0];
    const float* kv = (const float*)d_in[1];
    float* out = (float*)d_out;

    int nsm = 0;
    cudaDeviceGetAttribute(&nsm, cudaDevAttrMultiProcessorCount, 0);
    if (nsm <= 0 || nsm > UNITS) nsm = 128;

    prep_kernel<<<4096, 512>>>(q, kv);
    diag_kernel<<<2048, 256>>>(q, kv);

    cudaFuncSetAttribute(main_kernel, cudaFuncAttributeMaxDynamicSharedMemorySize,
                         SMEM_TOTAL);
    main_kernel<<<nsm, THREADS, SMEM_TOTAL>>>(nsm);

    out_kernel<<<BATCH * NSEQ / 256, 256>>>(out);
}

// round 10
// speedup vs baseline: 6.7662x; 1.8219x over previous
#include <cuda_runtime.h>
#include <cuda_fp16.h>
#include <cstdint>

#define DEVINL __device__ __forceinline__

// ---------------- problem constants ----------------
static constexpr int BATCH = 4;
static constexpr int NSEQ  = 4096;
static constexpr int DDIM  = 512;
// scale * log2(e): logits kept in log2 domain so epilogue is a bare ex2.approx
static constexpr float CLOG2E = 0.09016844005556021f;

// ---------------- tiling ----------------
static constexpr int MT    = 128;            // q rows per unit
static constexpr int NTILE = 256;            // kv rows per unit
static constexpr int KC    = 64;             // k per chunk (128B smem rows)
static constexpr int QTILES = BATCH * NSEQ / MT;   // 128
static constexpr int NTC    = NSEQ / NTILE;        // 16
static constexpr int UNITS  = QTILES * NTC;        // 2048 work units
static constexpr int STAGES = 4;
static constexpr int THREADS = 256;                // 8 warps: 2 M x 4 N

static constexpr int AB  = MT * KC * 2;          // 16384
static constexpr int BB  = NTILE * KC * 2;       // 32768
static constexpr int STB = AB + BB;              // 49152 per stage
static constexpr int SMEM_TOTAL = 1024 + STAGES * STB;   // 197632

// ---------------- scratch (device globals: no allocs allowed) ----------------
__device__ __align__(1024) __half g_q16[(size_t)BATCH * NSEQ * DDIM];  // q * CLOG2E
__device__ __align__(1024) __half g_k16[(size_t)BATCH * NSEQ * DDIM];  // k
__device__ float g_diagexp[BATCH * NSEQ];
__device__ float g_rsum[BATCH * NSEQ];

// ---------------- PTX helpers ----------------
DEVINL uint32_t smem_u32(const void* p) {
    uint32_t a;
    asm("{ .reg .u64 t; cvta.to.shared.u64 t, %1; cvt.u32.u64 %0, t; }"
        : "=r"(a) : "l"(p));
    return a;
}
DEVINL uint32_t sw128(uint32_t off) { return off ^ ((off >> 3) & 0x70); }

DEVINL void cp_async16(uint32_t dst, const void* src) {
    asm volatile("cp.async.cg.shared.global [%0], [%1], 16;"
                 :: "r"(dst), "l"(src) : "memory");
}
DEVINL void cp_commit() { asm volatile("cp.async.commit_group;" ::: "memory"); }
template <int N>
DEVINL void cp_wait_group() { asm volatile("cp.async.wait_group %0;" :: "n"(N) : "memory"); }

DEVINL void ldsm4(uint32_t (&r)[4], uint32_t addr) {
    asm volatile("ldmatrix.sync.aligned.m8n8.x4.shared.b16 {%0,%1,%2,%3}, [%4];"
                 : "=r"(r[0]), "=r"(r[1]), "=r"(r[2]), "=r"(r[3]) : "r"(addr));
}
// fp16-accumulate MMA: D (2 regs = 4 halves) += A*B
DEVINL void mma_f16acc(uint32_t* d, const uint32_t* a, uint32_t b0, uint32_t b1) {
    asm volatile(
        "mma.sync.aligned.m16n8k16.row.col.f16.f16.f16.f16 "
        "{%0,%1}, {%2,%3,%4,%5}, {%6,%7}, {%0,%1};"
        : "+r"(d[0]), "+r"(d[1])
        : "r"(a[0]), "r"(a[1]), "r"(a[2]), "r"(a[3]), "r"(b0), "r"(b1));
}
DEVINL float ex2(float x) {
    float y;
    asm("ex2.approx.ftz.f32 %0, %1;" : "=f"(y) : "f"(x));
    return y;
}

// ---------------- prep: q -> fp16 (scaled), k -> fp16 ----------------
__global__ void __launch_bounds__(512) prep_kernel(const float* __restrict__ q,
                                                   const float* __restrict__ kv) {
    size_t idx = (size_t)blockIdx.x * 512 + threadIdx.x;  // float4 id (exact grid)
    size_t o   = idx << 2;

    {
        float4 a = reinterpret_cast<const float4*>(q)[idx];
        __half2* p = reinterpret_cast<__half2*>(g_q16 + o);
        p[0] = __halves2half2(__float2half(a.x * CLOG2E), __float2half(a.y * CLOG2E));
        p[1] = __halves2half2(__float2half(a.z * CLOG2E), __float2half(a.w * CLOG2E));
    }
    {
        float4 a = reinterpret_cast<const float4*>(kv)[idx];
        __half2* p = reinterpret_cast<__half2*>(g_k16 + o);
        p[0] = __halves2half2(__float2half(a.x), __float2half(a.y));
        p[1] = __halves2half2(__float2half(a.z), __float2half(a.w));
    }
}

// ---------------- exact fp32 diagonal + zero the row-sum accumulators ----------------
__global__ void __launch_bounds__(256) diag_kernel(const float* __restrict__ q,
                                                   const float* __restrict__ kv) {
    int row  = blockIdx.x * 8 + (threadIdx.x >> 5);
    int lane = threadIdx.x & 31;
    const float* qr = q  + (size_t)row * DDIM;
    const float* kr = kv + (size_t)row * DDIM;
    float s = 0.f;
#pragma unroll
    for (int i = 0; i < 16; ++i) s += qr[lane + 32 * i] * kr[lane + 32 * i];
#pragma unroll
    for (int off = 16; off; off >>= 1) s += __shfl_xor_sync(0xffffffffu, s, off);
    if (lane == 0) {
        g_diagexp[row] = exp2f(CLOG2E * s);
        g_rsum[row] = 0.f;
    }
}

// ---------------- main GEMM + normalizer: persistent over all SMs ----------------
__global__ void __launch_bounds__(THREADS, 1) main_kernel(int nsm) {
    extern __shared__ char smem_raw[];
    const uint32_t st0 = (smem_u32(smem_raw) + 1023u) & ~1023u;

    const int tid  = threadIdx.x;
    const int wid  = tid >> 5;
    const int lane = tid & 31;
    const int bid  = blockIdx.x;

    // per-thread cp.async vector descriptors (16B vectors)
    // q tile: 128x64 fp16 = 1024 vectors -> 4/thread; k tile: 2048 -> 8/thread
    int qoff[4]; uint32_t qdst[4];
#pragma unroll
    for (int i = 0; i < 4; ++i) {
        int v = tid + i * THREADS, r = v >> 3, j = v & 7;
        qoff[i] = r * DDIM + j * 8;
        qdst[i] = sw128((uint32_t)(r * 128 + j * 16));
    }
    int koff[8]; uint32_t kdst[8];
#pragma unroll
    for (int i = 0; i < 8; ++i) {
        int v = tid + i * THREADS, r = v >> 3, j = v & 7;
        koff[i] = r * DDIM + j * 8;
        kdst[i] = sw128((uint32_t)(r * 128 + j * 16));
    }

    // unit u = nt*128 + qt : one wave shares a kv supertile (L2 reuse)
    auto issue = [&](int it) {
        const int u = bid + (it >> 3) * nsm;
        if (u >= UNITS) { cp_commit(); return; }   // keep group counts uniform
        const int qt = u & (QTILES - 1), nt = u >> 7, cc = it & 7;
        const uint32_t sA = st0 + (it & 3) * STB;
        const uint32_t sB = sA + AB;
        const __half* qs = g_q16 + (size_t)qt * MT * DDIM + cc * KC;
#pragma unroll
        for (int i = 0; i < 4; ++i) cp_async16(sA + qdst[i], qs + qoff[i]);
        const __half* ks = g_k16 +
            ((size_t)(qt >> 5) * NSEQ + (size_t)nt * NTILE) * DDIM + cc * KC;
#pragma unroll
        for (int i = 0; i < 8; ++i) cp_async16(sB + kdst[i], ks + koff[i]);
        cp_commit();
    };

    // warp tile: 2 M-warps x 4 N-warps, each 64x64
    const int m0 = (wid & 1) * 64;
    const int n0 = (wid >> 1) * 64;
    const int lr  = lane & 15;          // ldmatrix row within 16
    const int lcb = (lane >> 4) * 16;   // ldmatrix 16B column group

    uint32_t aBase[4], aSw[4], bBase[4], bSw[4];
#pragma unroll
    for (int f = 0; f < 4; ++f) {
        int ra = m0 + f * 16 + lr;
        aBase[f] = (uint32_t)(ra * 128); aSw[f] = (uint32_t)((ra & 7) << 4);
        int rb = n0 + f * 16 + lr;
        bBase[f] = (uint32_t)(rb * 128); bSw[f] = (uint32_t)((rb & 7) << 4);
    }

    // fp16 accumulators
    uint32_t ch[4][8][2];
#pragma unroll
    for (int mf = 0; mf < 4; ++mf)
#pragma unroll
        for (int nf = 0; nf < 8; ++nf) { ch[mf][nf][0] = 0u; ch[mf][nf][1] = 0u; }

    const int nunits = (UNITS - bid + nsm - 1) / nsm;   // bid < nsm <= UNITS
    const int nits   = nunits * 8;

    issue(0);
    issue(1);
    issue(2);

    for (int it = 0; it < nits; ++it) {
        cp_wait_group<2>();
        __syncthreads();
        issue(it + 3);

        const uint32_t sA = st0 + (it & 3) * STB;
        const uint32_t sB = sA + AB;

#pragma unroll
        for (int kk = 0; kk < 4; ++kk) {
            const uint32_t cb = (uint32_t)(kk * 32) + lcb;
            uint32_t a[4][4], b[4][4];
#pragma unroll
            for (int f = 0; f < 4; ++f) ldsm4(b[f], sB + bBase[f] + (cb ^ bSw[f]));
#pragma unroll
            for (int f = 0; f < 4; ++f) ldsm4(a[f], sA + aBase[f] + (cb ^ aSw[f]));
#pragma unroll
            for (int mf = 0; mf < 4; ++mf)
#pragma unroll
                for (int g = 0; g < 4; ++g) {
                    mma_f16acc(ch[mf][2 * g],     a[mf], b[g][0], b[g][2]);
                    mma_f16acc(ch[mf][2 * g + 1], a[mf], b[g][1], b[g][3]);
                }
        }

        if ((it & 7) == 7) {
            // unit epilogue: rowsum of 2^score -> global accumulators
            const int qt = (bid + (it >> 3) * nsm) & (QTILES - 1);
            float* rs = g_rsum + qt * MT;
#pragma unroll
            for (int mf = 0; mf < 4; ++mf) {
                float s0 = 0.f, s1 = 0.f;
#pragma unroll
                for (int nf = 0; nf < 8; ++nf) {
                    float2 h0 = __half22float2(*reinterpret_cast<__half2*>(&ch[mf][nf][0]));
                    float2 h1 = __half22float2(*reinterpret_cast<__half2*>(&ch[mf][nf][1]));
                    s0 += ex2(h0.x) + ex2(h0.y);
                    s1 += ex2(h1.x) + ex2(h1.y);
                    ch[mf][nf][0] = 0u; ch[mf][nf][1] = 0u;
                }
                s0 += __shfl_xor_sync(0xffffffffu, s0, 1);
                s0 += __shfl_xor_sync(0xffffffffu, s0, 2);
                s1 += __shfl_xor_sync(0xffffffffu, s1, 1);
                s1 += __shfl_xor_sync(0xffffffffu, s1, 2);
                if ((lane & 3) == 0) {
                    atomicAdd(&rs[m0 + mf * 16 + (lane >> 2)], s0);
                    atomicAdd(&rs[m0 + mf * 16 + 8 + (lane >> 2)], s1);
                }
            }
        }
    }
}

// ---------------- final: out = diagexp / rowsum ----------------
__global__ void __launch_bounds__(256) out_kernel(float* __restrict__ out) {
    int row = blockIdx.x * 256 + threadIdx.x;
    out[row] = g_diagexp[row] / g_rsum[row];
}

extern "C" void kernel_launch(void* const* d_in, const int* in_sizes, int n_in,
                              void* d_out, int out_size) {
    const float* q  = (const float*)d_in[0];
    const float* kv = (const float*)d_in[1];
    float* out = (float*)d_out;

    int nsm = 0;
    cudaDeviceGetAttribute(&nsm, cudaDevAttrMultiProcessorCount, 0);
    if (nsm <= 0 || nsm > UNITS) nsm = 128;

    prep_kernel<<<4096, 512>>>(q, kv);
    diag_kernel<<<2048, 256>>>(q, kv);

    cudaFuncSetAttribute(main_kernel, cudaFuncAttributeMaxDynamicSharedMemorySize,
                         SMEM_TOTAL);
    main_kernel<<<nsm, THREADS, SMEM_TOTAL>>>(nsm);

    out_kernel<<<BATCH * NSEQ / 256, 256>>>(out);
}

// round 11
// speedup vs baseline: 6.9742x; 1.0307x over previous
#include <cuda_runtime.h>
#include <cuda_fp16.h>
#include <cstdint>

#define DEVINL __device__ __forceinline__

// ---------------- problem constants ----------------
static constexpr int BATCH = 4;
static constexpr int NSEQ  = 4096;
static constexpr int DDIM  = 512;
// scale * log2(e): logits kept in log2 domain so epilogue is a bare ex2.approx
static constexpr float CLOG2E = 0.09016844005556021f;

// ---------------- tiling ----------------
static constexpr int MT    = 128;            // q rows per unit
static constexpr int NTILE = 256;            // kv rows per unit
static constexpr int KC    = 64;             // k per chunk (128B smem rows)
static constexpr int QTILES = BATCH * NSEQ / MT;   // 128
static constexpr int NTC    = NSEQ / NTILE;        // 16
static constexpr int UNITS  = QTILES * NTC;        // 2048 work units
static constexpr int STAGES = 4;
static constexpr int THREADS = 256;                // 8 warps: 2 M x 4 N

static constexpr int AB  = MT * KC * 2;          // 16384
static constexpr int BB  = NTILE * KC * 2;       // 32768
static constexpr int STB = AB + BB;              // 49152 per stage
static constexpr int SMEM_TOTAL = 1024 + STAGES * STB;   // 197632

// ---------------- scratch (device globals: no allocs allowed) ----------------
__device__ __align__(1024) __half g_q16[(size_t)BATCH * NSEQ * DDIM];  // q * CLOG2E
__device__ __align__(1024) __half g_k16[(size_t)BATCH * NSEQ * DDIM];  // k
__device__ float g_diagexp[BATCH * NSEQ];
__device__ float g_rsum[BATCH * NSEQ];

// ---------------- PTX helpers ----------------
DEVINL uint32_t smem_u32(const void* p) {
    uint32_t a;
    asm("{ .reg .u64 t; cvta.to.shared.u64 t, %1; cvt.u32.u64 %0, t; }"
        : "=r"(a) : "l"(p));
    return a;
}
DEVINL uint32_t sw128(uint32_t off) { return off ^ ((off >> 3) & 0x70); }

DEVINL void cp_async16(uint32_t dst, const void* src) {
    asm volatile("cp.async.cg.shared.global [%0], [%1], 16;"
                 :: "r"(dst), "l"(src) : "memory");
}
DEVINL void cp_commit() { asm volatile("cp.async.commit_group;" ::: "memory"); }
template <int N>
DEVINL void cp_wait_group() { asm volatile("cp.async.wait_group %0;" :: "n"(N) : "memory"); }

DEVINL void ldsm4(uint32_t (&r)[4], uint32_t addr) {
    asm volatile("ldmatrix.sync.aligned.m8n8.x4.shared.b16 {%0,%1,%2,%3}, [%4];"
                 : "=r"(r[0]), "=r"(r[1]), "=r"(r[2]), "=r"(r[3]) : "r"(addr));
}
// fp16-accumulate MMA: D (2 regs = 4 halves) += A*B
DEVINL void mma_f16acc(uint32_t* d, const uint32_t* a, uint32_t b0, uint32_t b1) {
    asm volatile(
        "mma.sync.aligned.m16n8k16.row.col.f16.f16.f16.f16 "
        "{%0,%1}, {%2,%3,%4,%5}, {%6,%7}, {%0,%1};"
        : "+r"(d[0]), "+r"(d[1])
        : "r"(a[0]), "r"(a[1]), "r"(a[2]), "r"(a[3]), "r"(b0), "r"(b1));
}
// packed fp16x2 2^x
DEVINL uint32_t ex2h2(uint32_t x) {
    uint32_t y;
    asm("ex2.approx.f16x2 %0, %1;" : "=r"(y) : "r"(x));
    return y;
}

// ---------------- prep: convert to fp16 + fused exact fp32 diagonal ----------------
// 512 threads = 4 rows/block (128 threads per 512-elem row, 4 warps/row)
__global__ void __launch_bounds__(512) prep_kernel(const float* __restrict__ q,
                                                   const float* __restrict__ kv) {
    __shared__ float part[16];   // 4 rows x 4 warps

    size_t idx = (size_t)blockIdx.x * 512 + threadIdx.x;  // float4 id (exact grid)
    size_t o   = idx << 2;

    float4 a = reinterpret_cast<const float4*>(q)[idx];
    float4 b = reinterpret_cast<const float4*>(kv)[idx];

    {
        __half2* p = reinterpret_cast<__half2*>(g_q16 + o);
        p[0] = __halves2half2(__float2half(a.x * CLOG2E), __float2half(a.y * CLOG2E));
        p[1] = __halves2half2(__float2half(a.z * CLOG2E), __float2half(a.w * CLOG2E));
    }
    {
        __half2* p = reinterpret_cast<__half2*>(g_k16 + o);
        p[0] = __halves2half2(__float2half(b.x), __float2half(b.y));
        p[1] = __halves2half2(__float2half(b.z), __float2half(b.w));
    }

    // fused diagonal: partial dot of this thread's 4 elements (exact fp32 inputs)
    float s = a.x * b.x + a.y * b.y + a.z * b.z + a.w * b.w;
#pragma unroll
    for (int off = 16; off; off >>= 1) s += __shfl_xor_sync(0xffffffffu, s, off);
    const int w = threadIdx.x >> 5;
    if ((threadIdx.x & 31) == 0) part[w] = s;
    __syncthreads();
    if (threadIdx.x < 4) {
        const int row = blockIdx.x * 4 + threadIdx.x;
        float d = part[threadIdx.x * 4] + part[threadIdx.x * 4 + 1]
                + part[threadIdx.x * 4 + 2] + part[threadIdx.x * 4 + 3];
        g_diagexp[row] = exp2f(CLOG2E * d);
        g_rsum[row] = 0.f;
    }
}

// ---------------- main GEMM + normalizer: persistent over all SMs ----------------
__global__ void __launch_bounds__(THREADS, 1) main_kernel(int nsm) {
    extern __shared__ char smem_raw[];
    const uint32_t st0 = (smem_u32(smem_raw) + 1023u) & ~1023u;

    const int tid  = threadIdx.x;
    const int wid  = tid >> 5;
    const int lane = tid & 31;
    const int bid  = blockIdx.x;

    // per-thread cp.async vector descriptors (16B vectors)
    int qoff[4]; uint32_t qdst[4];
#pragma unroll
    for (int i = 0; i < 4; ++i) {
        int v = tid + i * THREADS, r = v >> 3, j = v & 7;
        qoff[i] = r * DDIM + j * 8;
        qdst[i] = sw128((uint32_t)(r * 128 + j * 16));
    }
    int koff[8]; uint32_t kdst[8];
#pragma unroll
    for (int i = 0; i < 8; ++i) {
        int v = tid + i * THREADS, r = v >> 3, j = v & 7;
        koff[i] = r * DDIM + j * 8;
        kdst[i] = sw128((uint32_t)(r * 128 + j * 16));
    }

    // unit u = nt*128 + qt : one wave shares a kv supertile (L2 reuse)
    auto issue = [&](int it) {
        const int u = bid + (it >> 3) * nsm;
        if (u >= UNITS) { cp_commit(); return; }   // keep group counts uniform
        const int qt = u & (QTILES - 1), nt = u >> 7, cc = it & 7;
        const uint32_t sA = st0 + (it & 3) * STB;
        const uint32_t sB = sA + AB;
        const __half* qs = g_q16 + (size_t)qt * MT * DDIM + cc * KC;
#pragma unroll
        for (int i = 0; i < 4; ++i) cp_async16(sA + qdst[i], qs + qoff[i]);
        const __half* ks = g_k16 +
            ((size_t)(qt >> 5) * NSEQ + (size_t)nt * NTILE) * DDIM + cc * KC;
#pragma unroll
        for (int i = 0; i < 8; ++i) cp_async16(sB + kdst[i], ks + koff[i]);
        cp_commit();
    };

    // warp tile: 2 M-warps x 4 N-warps, each 64x64
    const int m0 = (wid & 1) * 64;
    const int n0 = (wid >> 1) * 64;
    const int lr  = lane & 15;          // ldmatrix row within 16
    const int lcb = (lane >> 4) * 16;   // ldmatrix 16B column group

    uint32_t aBase[4], aSw[4], bBase[4], bSw[4];
#pragma unroll
    for (int f = 0; f < 4; ++f) {
        int ra = m0 + f * 16 + lr;
        aBase[f] = (uint32_t)(ra * 128); aSw[f] = (uint32_t)((ra & 7) << 4);
        int rb = n0 + f * 16 + lr;
        bBase[f] = (uint32_t)(rb * 128); bSw[f] = (uint32_t)((rb & 7) << 4);
    }

    // fp16 accumulators
    uint32_t ch[4][8][2];
#pragma unroll
    for (int mf = 0; mf < 4; ++mf)
#pragma unroll
        for (int nf = 0; nf < 8; ++nf) { ch[mf][nf][0] = 0u; ch[mf][nf][1] = 0u; }

    const int nunits = (UNITS - bid + nsm - 1) / nsm;   // bid < nsm <= UNITS
    const int nits   = nunits * 8;

    issue(0);
    issue(1);
    issue(2);

    for (int it = 0; it < nits; ++it) {
        cp_wait_group<2>();
        __syncthreads();
        issue(it + 3);

        const uint32_t sA = st0 + (it & 3) * STB;
        const uint32_t sB = sA + AB;

#pragma unroll
        for (int kk = 0; kk < 4; ++kk) {
            const uint32_t cb = (uint32_t)(kk * 32) + lcb;
            uint32_t a[4][4], b[4][4];
#pragma unroll
            for (int f = 0; f < 4; ++f) ldsm4(b[f], sB + bBase[f] + (cb ^ bSw[f]));
#pragma unroll
            for (int f = 0; f < 4; ++f) ldsm4(a[f], sA + aBase[f] + (cb ^ aSw[f]));
#pragma unroll
            for (int mf = 0; mf < 4; ++mf)
#pragma unroll
                for (int g = 0; g < 4; ++g) {
                    mma_f16acc(ch[mf][2 * g],     a[mf], b[g][0], b[g][2]);
                    mma_f16acc(ch[mf][2 * g + 1], a[mf], b[g][1], b[g][3]);
                }
        }

        if ((it & 7) == 7) {
            // unit epilogue: rowsum of 2^score via packed f16x2 ex2
            const int qt = (bid + (it >> 3) * nsm) & (QTILES - 1);
            float* rs = g_rsum + qt * MT;
#pragma unroll
            for (int mf = 0; mf < 4; ++mf) {
                float s0 = 0.f, s1 = 0.f;
#pragma unroll
                for (int nf = 0; nf < 8; ++nf) {
                    uint32_t e0 = ex2h2(ch[mf][nf][0]);
                    uint32_t e1 = ex2h2(ch[mf][nf][1]);
                    float2 f0 = __half22float2(*reinterpret_cast<__half2*>(&e0));
                    float2 f1 = __half22float2(*reinterpret_cast<__half2*>(&e1));
                    s0 += f0.x + f0.y;
                    s1 += f1.x + f1.y;
                    ch[mf][nf][0] = 0u; ch[mf][nf][1] = 0u;
                }
                s0 += __shfl_xor_sync(0xffffffffu, s0, 1);
                s0 += __shfl_xor_sync(0xffffffffu, s0, 2);
                s1 += __shfl_xor_sync(0xffffffffu, s1, 1);
                s1 += __shfl_xor_sync(0xffffffffu, s1, 2);
                if ((lane & 3) == 0) {
                    atomicAdd(&rs[m0 + mf * 16 + (lane >> 2)], s0);
                    atomicAdd(&rs[m0 + mf * 16 + 8 + (lane >> 2)], s1);
                }
            }
        }
    }
}

// ---------------- final: out = diagexp / rowsum ----------------
__global__ void __launch_bounds__(256) out_kernel(float* __restrict__ out) {
    int row = blockIdx.x * 256 + threadIdx.x;
    out[row] = g_diagexp[row] / g_rsum[row];
}

extern "C" void kernel_launch(void* const* d_in, const int* in_sizes, int n_in,
                              void* d_out, int out_size) {
    const float* q  = (const float*)d_in[0];
    const float* kv = (const float*)d_in[1];
    float* out = (float*)d_out;

    int nsm = 0;
    cudaDeviceGetAttribute(&nsm, cudaDevAttrMultiProcessorCount, 0);
    if (nsm <= 0 || nsm > UNITS) nsm = 128;

    prep_kernel<<<4096, 512>>>(q, kv);

    cudaFuncSetAttribute(main_kernel, cudaFuncAttributeMaxDynamicSharedMemorySize,
                         SMEM_TOTAL);
    main_kernel<<<nsm, THREADS, SMEM_TOTAL>>>(nsm);

    out_kernel<<<BATCH * NSEQ / 256, 256>>>(out);
}